// round 8
// baseline (speedup 1.0000x reference)
#include <cuda_runtime.h>
#include <math.h>

// Fixed shapes: x is (4,3,64,64) fp32
#define HW      4096
#define NCH     12
#define NOFF    16129        // 127*127 offsets
#define NBINS   7939
#define SOFF_N  1024         // staged offsets
#define CH      16           // chunk size
#define STRIDE  128          // padded plane row stride
#define R_TOP   20           // vertical zero margin (rows above and below)
#define ROWS_P  (64 + 2 * R_TOP)      // 104
#define PLANE_F (ROWS_P * STRIDE)     // 13312 floats = 52KB

struct Tables {
    int   off[NOFF];   // dy*STRIDE + dx   (hot path, padded-plane delta)
    float d2[NOFF];
    int   pk[NOFF];    // dy*65536 | (dx & 0xFFFF)  (cold tail, exact decode)
};

constexpr Tables make_tables() {
    Tables t{};
    int hist[NBINS] = {};
    for (int dy = -63; dy <= 63; ++dy)
        for (int dx = -63; dx <= 63; ++dx)
            hist[dy * dy + dx * dx]++;
    int start[NBINS] = {};
    int acc = 0;
    for (int b = 0; b < NBINS; ++b) { start[b] = acc; acc += hist[b]; }
    for (int dy = -63; dy <= 63; ++dy)
        for (int dx = -63; dx <= 63; ++dx) {
            int d2  = dy * dy + dx * dx;
            int pos = start[d2]++;
            t.off[pos] = dy * STRIDE + dx;
            t.d2[pos]  = (float)d2;
            t.pk[pos]  = dy * 65536 | (dx & 0xFFFF);
        }
    return t;
}

__device__ constexpr Tables g_tab = make_tables();

// d2 of the last staged entry -> guaranteed |dy|,|dx| bound for the hot path.
constexpr int d2_last_staged() {
    int hist[NBINS] = {};
    for (int dy = -63; dy <= 63; ++dy)
        for (int dx = -63; dx <= 63; ++dx)
            hist[dy * dy + dx * dx]++;
    int acc = 0;
    for (int b = 0; b < NBINS; ++b) { acc += hist[b]; if (acc >= SOFF_N) return b; }
    return NBINS - 1;
}
constexpr int isqrt_c(int v) { int s = 0; while ((s + 1) * (s + 1) <= v) ++s; return s; }
static_assert(isqrt_c(d2_last_staged()) <= R_TOP, "vertical margin too small");
static_assert(isqrt_c(d2_last_staged()) <= 32,    "horizontal margin too small");

// Deep-first block order: edge row-pairs (long scans) start first.
constexpr int mk_seg(int i) { return (i & 1) ? 31 - (i >> 1) : (i >> 1); }
__device__ constexpr int seg_order[32] = {
    mk_seg(0),  mk_seg(1),  mk_seg(2),  mk_seg(3),  mk_seg(4),  mk_seg(5),
    mk_seg(6),  mk_seg(7),  mk_seg(8),  mk_seg(9),  mk_seg(10), mk_seg(11),
    mk_seg(12), mk_seg(13), mk_seg(14), mk_seg(15), mk_seg(16), mk_seg(17),
    mk_seg(18), mk_seg(19), mk_seg(20), mk_seg(21), mk_seg(22), mk_seg(23),
    mk_seg(24), mk_seg(25), mk_seg(26), mk_seg(27), mk_seg(28), mk_seg(29),
    mk_seg(30), mk_seg(31)
};

// smem: plane 52KB + table-as-float4 8KB + reduction partials
#define SMEM_BYTES ((PLANE_F + SOFF_N * 2 + 64) * 4)

// 256 threads = 2 threads per pixel (role A/B), 128 consecutive pixels (2 rows).
// 32 blocks per channel, 384 blocks (fully resident in one wave).
__global__ __launch_bounds__(256) void k_main(const float* __restrict__ x,
                                              float* __restrict__ out) {
    extern __shared__ float smem[];
    float*  swp   = smem;                        // [104][128], zero margins all sides
    float4* soff4 = (float4*)(smem + PLANE_F);   // (lin0,d20,lin1,d21)
    float2* soff2 = (float2*)soff4;
    float*  red   = smem + PLANE_F + SOFF_N * 2; // 8 warp partials

    const int tid  = threadIdx.x;
    const int bc   = blockIdx.x >> 5;
    const int seg  = seg_order[blockIdx.x & 31];
    const int role = tid & 1;                    // A: offsets [0,8) of chunk; B: [8,16)
    const float* __restrict__ plane = x + bc * HW;

    // --- Prologue: zero margins, fill data, stage table (disjoint; one sync) ---
    // Top rows 0..19 and bottom rows 84..103: 40 rows * 32 f4 = 1280 f4.
    #pragma unroll
    for (int m = tid; m < 1280; m += 256) {
        int r = m >> 5, k = m & 31;
        int prow = (r < R_TOP) ? r : 64 + r;     // 0..19 or 84..103
        ((float4*)swp)[prow * 32 + k] = make_float4(0.f, 0.f, 0.f, 0.f);
    }
    // Side margins of the 64 data rows: 64 * 16 f4 (f4 cols 0..7 and 24..31).
    #pragma unroll
    for (int m = tid; m < 1024; m += 256) {
        int r = m >> 4, k = m & 15;
        ((float4*)swp)[(R_TOP + r) * 32 + (k < 8 ? k : k + 16)] =
            make_float4(0.f, 0.f, 0.f, 0.f);
    }
    // Data (f4 cols 8..23) + per-thread partial sum.
    float acc = 0.f;
    #pragma unroll
    for (int i = tid; i < 1024; i += 256) {
        int row = i >> 4, c4 = i & 15;
        float4 v = ((const float4*)plane)[i];
        ((float4*)swp)[(R_TOP + row) * 32 + 8 + c4] = v;
        acc += v.x + v.y + v.z + v.w;
    }
    // Interleaved offset table.
    #pragma unroll
    for (int i = tid; i < SOFF_N / 2; i += 256)
        soff4[i] = make_float4(__int_as_float(g_tab.off[2 * i]), g_tab.d2[2 * i],
                               __int_as_float(g_tab.off[2 * i + 1]), g_tab.d2[2 * i + 1]);
    // Butterfly reduce within warp (commutative fp adds: lane-identical).
    #pragma unroll
    for (int d = 16; d > 0; d >>= 1)
        acc += __shfl_xor_sync(0xFFFFFFFFu, acc, d);
    if ((tid & 31) == 0) red[tid >> 5] = acc;
    __syncthreads();
    float tot = ((red[0] + red[1]) + (red[2] + red[3]))
              + ((red[4] + red[5]) + (red[6] + red[7]));
    const float bound = 0.05f * tot;

    const int p  = seg * 128 + (tid >> 1);
    const int pi = p >> 6, pj = p & 63;
    const int pc = (pi + R_TOP) * STRIDE + 32 + pj;

    float cw   = 0.f;    // total weight of completed chunks (both roles)
    float qacc = 0.f;    // role-local d2-weighted partial
    float cw0  = 0.f, q0 = 0.f;
    int   t_cr = -1;
    bool  done = false;

    // --- Hot loop: no bounds checks (full zero margins); ballot every 4 chunks ---
    for (int t0 = 0; t0 < SOFF_N; t0 += 4 * CH) {
        #pragma unroll
        for (int c = 0; c < 4; ++c) {
            int tb = t0 + c * CH;
            const float4* eP = soff4 + ((tb >> 1) + role * 4);
            float4 e0 = eP[0], e1 = eP[1], e2 = eP[2], e3 = eP[3];
            float w0 = swp[pc + __float_as_int(e0.x)];
            float w1 = swp[pc + __float_as_int(e0.z)];
            float w2 = swp[pc + __float_as_int(e1.x)];
            float w3 = swp[pc + __float_as_int(e1.z)];
            float w4 = swp[pc + __float_as_int(e2.x)];
            float w5 = swp[pc + __float_as_int(e2.z)];
            float w6 = swp[pc + __float_as_int(e3.x)];
            float w7 = swp[pc + __float_as_int(e3.z)];
            float s = ((w0 + w1) + (w2 + w3)) + ((w4 + w5) + (w6 + w7));
            float q = ((w0 * e0.y + w1 * e0.w) + (w2 * e1.y + w3 * e1.w))
                    + ((w4 * e2.y + w5 * e2.w) + (w6 * e3.y + w7 * e3.w));
            float s16 = s + __shfl_xor_sync(0xFFFFFFFFu, s, 1);
            bool cross = (!done) & (cw + s16 >= bound);
            if (cross) { t_cr = tb; cw0 = cw; q0 = qacc; done = true; }
            cw   += s16;
            qacc += q;
        }
        if (__ballot_sync(0xFFFFFFFFu, !done) == 0u) break;
    }

    // --- Epilogue: combine role-local q, one uniform replay per thread ---
    float qsnap = done ? q0 : qacc;
    float cs0   = qsnap + __shfl_xor_sync(0xFFFFFFFFu, qsnap, 1);
    float cwX   = done ? cw0 : cw;

    float val = 0.f;
    bool  found = false;
    int   t_tail = NOFF;
    if (done) {
        float cwl = cwX, csl = cs0;
        float wv[CH], dv[CH];
        #pragma unroll
        for (int k = 0; k < CH; ++k) {
            float2 e = soff2[t_cr + k];
            wv[k] = swp[pc + __float_as_int(e.x)];
            dv[k] = e.y;
        }
        #pragma unroll
        for (int k = 0; k < CH; ++k) {
            cwl += wv[k];
            csl += dv[k] * wv[k];
            if (!found && cwl >= bound) {
                val = csl + dv[k] * (bound - cwl);
                found = true;
            }
        }
        if (!found) { t_tail = t_cr + CH; cwX = cwl; cs0 = csl; } // ulp slip
    } else {
        t_tail = SOFF_N;
    }

    // --- Cold exact tail (essentially never taken): global gathers, full range ---
    if (t_tail < NOFF) {
        float cwl = cwX, csl = cs0;
        #pragma unroll 1
        for (int t = t_tail; t < NOFF && !found; ++t) {
            int pk   = g_tab.pk[t];
            float d2 = g_tab.d2[t];
            int dy   = pk >> 16;
            int dx   = (int)(short)(pk & 0xFFFF);
            int ni   = pi + dy, nj = pj + dx;
            float w  = 0.f;
            if (((unsigned)ni < 64u) & ((unsigned)nj < 64u))
                w = plane[ni * 64 + nj];
            cwl += w;
            csl += d2 * w;
            if (cwl >= bound) { val = csl + d2 * (bound - cwl); found = true; }
        }
        if (!found) val = csl;
    }

    if (role == 0) out[bc * HW + p] = sqrtf(val / bound);
}

// ---------------------------------------------------------------------------
extern "C" void kernel_launch(void* const* d_in, const int* in_sizes, int n_in,
                              void* d_out, int out_size) {
    const float* x = (const float*)d_in[0];
    float* out = (float*)d_out;
    cudaFuncSetAttribute(k_main, cudaFuncAttributeMaxDynamicSharedMemorySize,
                         SMEM_BYTES);
    k_main<<<NCH * 32, 256, SMEM_BYTES>>>(x, out);
}

// round 10
// speedup vs baseline: 1.0578x; 1.0578x over previous
#include <cuda_runtime.h>
#include <math.h>

// Fixed shapes: x is (4,3,64,64) fp32
#define HW      4096
#define NCH     12
#define NOFF    16129        // 127*127 offsets
#define NBINS   7939
#define SOFF_N  1024         // staged offsets
#define CH      16           // chunk size
#define STRIDE  128          // padded plane row stride
#define R_TOP   20           // vertical zero margin
#define ROWS_P  (64 + 2 * R_TOP)      // 104
#define PLANE_F (ROWS_P * STRIDE)     // 13312 floats = 52KB

struct Tables {
    int   off[NOFF];   // dy*STRIDE + dx   (hot path, padded-plane delta)
    float d2[NOFF];
    int   pk[NOFF];    // dy*65536 | (dx & 0xFFFF)  (cold tail, exact decode)
};

constexpr Tables make_tables() {
    Tables t{};
    int hist[NBINS] = {};
    for (int dy = -63; dy <= 63; ++dy)
        for (int dx = -63; dx <= 63; ++dx)
            hist[dy * dy + dx * dx]++;
    int start[NBINS] = {};
    int acc = 0;
    for (int b = 0; b < NBINS; ++b) { start[b] = acc; acc += hist[b]; }
    for (int dy = -63; dy <= 63; ++dy)
        for (int dx = -63; dx <= 63; ++dx) {
            int d2  = dy * dy + dx * dx;
            int pos = start[d2]++;
            t.off[pos] = dy * STRIDE + dx;
            t.d2[pos]  = (float)d2;
            t.pk[pos]  = dy * 65536 | (dx & 0xFFFF);
        }
    return t;
}

__device__ constexpr Tables g_tab = make_tables();

constexpr int d2_last_staged() {
    int hist[NBINS] = {};
    for (int dy = -63; dy <= 63; ++dy)
        for (int dx = -63; dx <= 63; ++dx)
            hist[dy * dy + dx * dx]++;
    int acc = 0;
    for (int b = 0; b < NBINS; ++b) { acc += hist[b]; if (acc >= SOFF_N) return b; }
    return NBINS - 1;
}
constexpr int isqrt_c(int v) { int s = 0; while ((s + 1) * (s + 1) <= v) ++s; return s; }
static_assert(isqrt_c(d2_last_staged()) <= R_TOP, "vertical margin too small");
static_assert(isqrt_c(d2_last_staged()) <= 32,    "horizontal margin too small");

// Depth-sorted row order (edge rows first): 0,63,1,62,...
constexpr int mk_row(int i) { return (i & 1) ? 63 - (i >> 1) : (i >> 1); }
struct RowOrder { int r[64]; };
constexpr RowOrder mk_order() {
    RowOrder o{};
    for (int i = 0; i < 64; ++i) o.r[i] = mk_row(i);
    return o;
}
__device__ constexpr RowOrder row_order = mk_order();

// smem: plane 52KB + table-as-float4 8KB + reduction partials
#define SMEM_BYTES ((PLANE_F + SOFF_N * 2 + 32) * 4)

// 128 threads = 2 threads per pixel (role A/B), one 64-pixel row per block.
// 64 blocks per channel, 768 blocks total — deepest rows launched first,
// channel-interleaved (LPT scheduling; ~1.7 residency waves rebalance the tail).
__global__ __launch_bounds__(128) void k_main(const float* __restrict__ x,
                                              float* __restrict__ out) {
    extern __shared__ float smem[];
    float*  swp   = smem;                        // [104][128], zero margins all sides
    float4* soff4 = (float4*)(smem + PLANE_F);   // (lin0,d20,lin1,d21)
    float2* soff2 = (float2*)soff4;
    float*  red   = smem + PLANE_F + SOFF_N * 2; // 4 warp partials

    const int tid  = threadIdx.x;
    const int bc   = blockIdx.x % NCH;           // channel varies fastest
    const int rr   = blockIdx.x / NCH;           // depth rank
    const int row  = row_order.r[rr];
    const int role = tid & 1;                    // A: offsets [0,8) of chunk; B: [8,16)
    const float* __restrict__ plane = x + bc * HW;

    // --- Prologue: zero margins, fill data, stage table (disjoint; one sync) ---
    #pragma unroll
    for (int m = tid; m < 1280; m += 128) {      // top+bottom margins: 40 rows * 32 f4
        int r = m >> 5, k = m & 31;
        int prow = (r < R_TOP) ? r : 64 + r;     // 0..19 or 84..103
        ((float4*)swp)[prow * 32 + k] = make_float4(0.f, 0.f, 0.f, 0.f);
    }
    #pragma unroll
    for (int m = tid; m < 1024; m += 128) {      // side margins: 64 rows * 16 f4
        int r = m >> 4, k = m & 15;
        ((float4*)swp)[(R_TOP + r) * 32 + (k < 8 ? k : k + 16)] =
            make_float4(0.f, 0.f, 0.f, 0.f);
    }
    float acc = 0.f;
    #pragma unroll
    for (int i = tid; i < 1024; i += 128) {      // data + per-thread partial sum
        int r = i >> 4, c4 = i & 15;
        float4 v = ((const float4*)plane)[i];
        ((float4*)swp)[(R_TOP + r) * 32 + 8 + c4] = v;
        acc += v.x + v.y + v.z + v.w;
    }
    #pragma unroll
    for (int i = tid; i < SOFF_N / 2; i += 128)  // interleaved offset table
        soff4[i] = make_float4(__int_as_float(g_tab.off[2 * i]), g_tab.d2[2 * i],
                               __int_as_float(g_tab.off[2 * i + 1]), g_tab.d2[2 * i + 1]);
    #pragma unroll
    for (int d = 16; d > 0; d >>= 1)             // butterfly: lane-identical
        acc += __shfl_xor_sync(0xFFFFFFFFu, acc, d);
    if ((tid & 31) == 0) red[tid >> 5] = acc;
    __syncthreads();
    const float bound = 0.05f * ((red[0] + red[1]) + (red[2] + red[3]));

    const int pj = tid >> 1;                     // column 0..63
    const int pi = row;
    const int pc = (pi + R_TOP) * STRIDE + 32 + pj;

    float cw   = 0.f;    // total weight of completed chunks (both roles)
    float qacc = 0.f;    // role-local d2-weighted partial
    float cw0  = 0.f, q0 = 0.f;
    int   t_cr = -1;
    bool  done = false;

    // --- Hot loop: no bounds checks; ballot every 2 chunks ---
    for (int t0 = 0; t0 < SOFF_N; t0 += 2 * CH) {
        #pragma unroll
        for (int c = 0; c < 2; ++c) {
            int tb = t0 + c * CH;
            const float4* eP = soff4 + ((tb >> 1) + role * 4);
            float4 e0 = eP[0], e1 = eP[1], e2 = eP[2], e3 = eP[3];
            float w0 = swp[pc + __float_as_int(e0.x)];
            float w1 = swp[pc + __float_as_int(e0.z)];
            float w2 = swp[pc + __float_as_int(e1.x)];
            float w3 = swp[pc + __float_as_int(e1.z)];
            float w4 = swp[pc + __float_as_int(e2.x)];
            float w5 = swp[pc + __float_as_int(e2.z)];
            float w6 = swp[pc + __float_as_int(e3.x)];
            float w7 = swp[pc + __float_as_int(e3.z)];
            float s = ((w0 + w1) + (w2 + w3)) + ((w4 + w5) + (w6 + w7));
            float q = ((w0 * e0.y + w1 * e0.w) + (w2 * e1.y + w3 * e1.w))
                    + ((w4 * e2.y + w5 * e2.w) + (w6 * e3.y + w7 * e3.w));
            float s16 = s + __shfl_xor_sync(0xFFFFFFFFu, s, 1);
            bool cross = (!done) & (cw + s16 >= bound);
            if (cross) { t_cr = tb; cw0 = cw; q0 = qacc; done = true; }
            cw   += s16;
            qacc += q;
        }
        if (__ballot_sync(0xFFFFFFFFu, !done) == 0u) break;
    }

    // --- Epilogue: combine role-local q, one uniform replay per thread ---
    float qsnap = done ? q0 : qacc;
    float cs0   = qsnap + __shfl_xor_sync(0xFFFFFFFFu, qsnap, 1);
    float cwX   = done ? cw0 : cw;

    float val = 0.f;
    bool  found = false;
    int   t_tail = NOFF;
    if (done) {
        float cwl = cwX, csl = cs0;
        float wv[CH], dv[CH];
        #pragma unroll
        for (int k = 0; k < CH; ++k) {
            float2 e = soff2[t_cr + k];
            wv[k] = swp[pc + __float_as_int(e.x)];
            dv[k] = e.y;
        }
        #pragma unroll
        for (int k = 0; k < CH; ++k) {
            cwl += wv[k];
            csl += dv[k] * wv[k];
            if (!found && cwl >= bound) {
                val = csl + dv[k] * (bound - cwl);
                found = true;
            }
        }
        if (!found) { t_tail = t_cr + CH; cwX = cwl; cs0 = csl; } // ulp slip
    } else {
        t_tail = SOFF_N;
    }

    // --- Cold exact tail (essentially never taken): global gathers, full range ---
    if (t_tail < NOFF) {
        float cwl = cwX, csl = cs0;
        #pragma unroll 1
        for (int t = t_tail; t < NOFF && !found; ++t) {
            int pk   = g_tab.pk[t];
            float d2 = g_tab.d2[t];
            int dy   = pk >> 16;
            int dx   = (int)(short)(pk & 0xFFFF);
            int ni   = pi + dy, nj = pj + dx;
            float w  = 0.f;
            if (((unsigned)ni < 64u) & ((unsigned)nj < 64u))
                w = plane[ni * 64 + nj];
            cwl += w;
            csl += d2 * w;
            if (cwl >= bound) { val = csl + d2 * (bound - cwl); found = true; }
        }
        if (!found) val = csl;
    }

    if (role == 0) out[bc * HW + pi * 64 + pj] = sqrtf(val / bound);
}

// ---------------------------------------------------------------------------
extern "C" void kernel_launch(void* const* d_in, const int* in_sizes, int n_in,
                              void* d_out, int out_size) {
    const float* x = (const float*)d_in[0];
    float* out = (float*)d_out;
    cudaFuncSetAttribute(k_main, cudaFuncAttributeMaxDynamicSharedMemorySize,
                         SMEM_BYTES);
    k_main<<<NCH * 64, 128, SMEM_BYTES>>>(x, out);
}

// round 12
// speedup vs baseline: 1.0739x; 1.0152x over previous
#include <cuda_runtime.h>
#include <math.h>

// Fixed shapes: x is (4,3,64,64) fp32
#define HW      4096
#define NCH     12
#define NOFF    16129        // 127*127 offsets
#define NBINS   7939
#define SOFF_N  1024         // staged offsets
#define CH      16           // chunk size
#define STRIDE  128          // window row stride
#define R_C     20           // window center slot (vertical margin)
#define WIN     40           // window rows
#define PLANE_F (WIN * STRIDE)       // 5120 floats = 20KB

struct Tables {
    int   off[NOFF];   // dy*STRIDE + dx   (hot path, window delta)
    float d2[NOFF];
    int   pk[NOFF];    // dy*65536 | (dx & 0xFFFF)  (cold tail, exact decode)
};

constexpr Tables make_tables() {
    Tables t{};
    int hist[NBINS] = {};
    for (int dy = -63; dy <= 63; ++dy)
        for (int dx = -63; dx <= 63; ++dx)
            hist[dy * dy + dx * dx]++;
    int start[NBINS] = {};
    int acc = 0;
    for (int b = 0; b < NBINS; ++b) { start[b] = acc; acc += hist[b]; }
    for (int dy = -63; dy <= 63; ++dy)
        for (int dx = -63; dx <= 63; ++dx) {
            int d2  = dy * dy + dx * dx;
            int pos = start[d2]++;
            t.off[pos] = dy * STRIDE + dx;
            t.d2[pos]  = (float)d2;
            t.pk[pos]  = dy * 65536 | (dx & 0xFFFF);
        }
    return t;
}

__device__ constexpr Tables g_tab = make_tables();

constexpr int d2_last_staged() {
    int hist[NBINS] = {};
    for (int dy = -63; dy <= 63; ++dy)
        for (int dx = -63; dx <= 63; ++dx)
            hist[dy * dy + dx * dx]++;
    int acc = 0;
    for (int b = 0; b < NBINS; ++b) { acc += hist[b]; if (acc >= SOFF_N) return b; }
    return NBINS - 1;
}
constexpr int isqrt_c(int v) { int s = 0; while ((s + 1) * (s + 1) <= v) ++s; return s; }
static_assert(isqrt_c(d2_last_staged()) <= R_C - 2,  "vertical window too small");
static_assert(isqrt_c(d2_last_staged()) <= 32,       "horizontal margin too small");

// Depth-sorted row order (edge rows first): 0,63,1,62,...
constexpr int mk_row(int i) { return (i & 1) ? 63 - (i >> 1) : (i >> 1); }
struct RowOrder { int r[64]; };
constexpr RowOrder mk_order() {
    RowOrder o{};
    for (int i = 0; i < 64; ++i) o.r[i] = mk_row(i);
    return o;
}
__device__ constexpr RowOrder row_order = mk_order();

// smem: window 20KB + table-as-float4 8KB + reduction partials
#define SMEM_BYTES ((PLANE_F + SOFF_N * 2 + 32) * 4)

// 128 threads = 2 threads per pixel (role A/B), one 64-pixel row per block.
// 64 blocks per channel, 768 blocks — ~29KB smem -> whole grid resident
// (~5.2 blocks/SM), depth-interleaved so deep blocks spread across SMs.
__global__ __launch_bounds__(128) void k_main(const float* __restrict__ x,
                                              float* __restrict__ out) {
    extern __shared__ float smem[];
    float*  swp   = smem;                        // [40][128] window, zero margins
    float4* soff4 = (float4*)(smem + PLANE_F);   // (lin0,d20,lin1,d21)
    float2* soff2 = (float2*)soff4;
    float*  red   = smem + PLANE_F + SOFF_N * 2; // 4 warp partials

    const int tid  = threadIdx.x;
    const int bc   = blockIdx.x % NCH;           // channel varies fastest
    const int rr   = blockIdx.x / NCH;           // depth rank
    const int pi   = row_order.r[rr];
    const int role = tid & 1;                    // A: offsets [0,8) of chunk; B: [8,16)
    const float* __restrict__ plane = x + bc * HW;

    // --- Prologue 1: zero the whole window (race-free vs fill via sync) ---
    #pragma unroll
    for (int m = tid; m < WIN * 32; m += 128)    // 1280 f4, 10 per thread
        ((float4*)swp)[m] = make_float4(0.f, 0.f, 0.f, 0.f);
    // Stage interleaved offset table (disjoint smem region).
    #pragma unroll
    for (int i = tid; i < SOFF_N / 2; i += 128)
        soff4[i] = make_float4(__int_as_float(g_tab.off[2 * i]), g_tab.d2[2 * i],
                               __int_as_float(g_tab.off[2 * i + 1]), g_tab.d2[2 * i + 1]);
    __syncthreads();

    // --- Prologue 2: full-plane sum (for bound) + windowed fill ---
    float acc = 0.f;
    #pragma unroll
    for (int i = tid; i < 1024; i += 128) {      // 8 f4 per thread
        float4 v = ((const float4*)plane)[i];
        acc += v.x + v.y + v.z + v.w;
        int rg   = i >> 4;                       // global row of this f4
        int slot = rg - pi + R_C;
        if ((unsigned)slot < (unsigned)WIN)
            ((float4*)swp)[slot * 32 + 8 + (i & 15)] = v;
    }
    #pragma unroll
    for (int d = 16; d > 0; d >>= 1)             // butterfly: lane-identical
        acc += __shfl_xor_sync(0xFFFFFFFFu, acc, d);
    if ((tid & 31) == 0) red[tid >> 5] = acc;
    __syncthreads();
    const float bound = 0.05f * ((red[0] + red[1]) + (red[2] + red[3]));

    const int pj = tid >> 1;                     // column 0..63
    const int pc = R_C * STRIDE + 32 + pj;       // window-centered

    float cw   = 0.f;    // total weight of completed chunks (both roles)
    float qacc = 0.f;    // role-local d2-weighted partial
    float cw0  = 0.f, q0 = 0.f;
    int   t_cr = -1;
    bool  done = false;

    // --- Hot loop: no bounds checks; ballot every 2 chunks ---
    for (int t0 = 0; t0 < SOFF_N; t0 += 2 * CH) {
        #pragma unroll
        for (int c = 0; c < 2; ++c) {
            int tb = t0 + c * CH;
            const float4* eP = soff4 + ((tb >> 1) + role * 4);
            float4 e0 = eP[0], e1 = eP[1], e2 = eP[2], e3 = eP[3];
            float w0 = swp[pc + __float_as_int(e0.x)];
            float w1 = swp[pc + __float_as_int(e0.z)];
            float w2 = swp[pc + __float_as_int(e1.x)];
            float w3 = swp[pc + __float_as_int(e1.z)];
            float w4 = swp[pc + __float_as_int(e2.x)];
            float w5 = swp[pc + __float_as_int(e2.z)];
            float w6 = swp[pc + __float_as_int(e3.x)];
            float w7 = swp[pc + __float_as_int(e3.z)];
            float s = ((w0 + w1) + (w2 + w3)) + ((w4 + w5) + (w6 + w7));
            float q = ((w0 * e0.y + w1 * e0.w) + (w2 * e1.y + w3 * e1.w))
                    + ((w4 * e2.y + w5 * e2.w) + (w6 * e3.y + w7 * e3.w));
            float s16 = s + __shfl_xor_sync(0xFFFFFFFFu, s, 1);
            bool cross = (!done) & (cw + s16 >= bound);
            if (cross) { t_cr = tb; cw0 = cw; q0 = qacc; done = true; }
            cw   += s16;
            qacc += q;
        }
        if (__ballot_sync(0xFFFFFFFFu, !done) == 0u) break;
    }

    // --- Epilogue: combine role-local q, one uniform replay per thread ---
    float qsnap = done ? q0 : qacc;
    float cs0   = qsnap + __shfl_xor_sync(0xFFFFFFFFu, qsnap, 1);
    float cwX   = done ? cw0 : cw;

    float val = 0.f;
    bool  found = false;
    int   t_tail = NOFF;
    if (done) {
        float cwl = cwX, csl = cs0;
        float wv[CH], dv[CH];
        #pragma unroll
        for (int k = 0; k < CH; ++k) {
            float2 e = soff2[t_cr + k];
            wv[k] = swp[pc + __float_as_int(e.x)];
            dv[k] = e.y;
        }
        #pragma unroll
        for (int k = 0; k < CH; ++k) {
            cwl += wv[k];
            csl += dv[k] * wv[k];
            if (!found && cwl >= bound) {
                val = csl + dv[k] * (bound - cwl);
                found = true;
            }
        }
        if (!found) { t_tail = t_cr + CH; cwX = cwl; cs0 = csl; } // ulp slip
    } else {
        t_tail = SOFF_N;
    }

    // --- Cold exact tail (essentially never taken): global gathers, full range ---
    if (t_tail < NOFF) {
        float cwl = cwX, csl = cs0;
        #pragma unroll 1
        for (int t = t_tail; t < NOFF && !found; ++t) {
            int pk   = g_tab.pk[t];
            float d2 = g_tab.d2[t];
            int dy   = pk >> 16;
            int dx   = (int)(short)(pk & 0xFFFF);
            int ni   = pi + dy, nj = pj + dx;
            float w  = 0.f;
            if (((unsigned)ni < 64u) & ((unsigned)nj < 64u))
                w = plane[ni * 64 + nj];
            cwl += w;
            csl += d2 * w;
            if (cwl >= bound) { val = csl + d2 * (bound - cwl); found = true; }
        }
        if (!found) val = csl;
    }

    if (role == 0) out[bc * HW + pi * 64 + pj] = sqrtf(val / bound);
}

// ---------------------------------------------------------------------------
extern "C" void kernel_launch(void* const* d_in, const int* in_sizes, int n_in,
                              void* d_out, int out_size) {
    const float* x = (const float*)d_in[0];
    float* out = (float*)d_out;
    cudaFuncSetAttribute(k_main, cudaFuncAttributeMaxDynamicSharedMemorySize,
                         SMEM_BYTES);
    k_main<<<NCH * 64, 128, SMEM_BYTES>>>(x, out);
}